// round 12
// baseline (speedup 1.0000x reference)
#include <cuda_runtime.h>
#include <math.h>

#define MAXN 100000
#define MAXE 1600000
#define SCAN_CH 512
#define MAXNB 256   // >= ceil(MAXN/SCAN_CH) = 196

// ---------------- scratch (device-code-only globals; see round-2 postmortem)
// INVARIANT: g_degi and g_look are all-zero at entry of every kernel_launch.
// Statically zero-initialized for the first call; k_out3 re-zeroes them at the
// end of every call (graph replays therefore always start clean).
__device__ __align__(16) float g_agg[(size_t)MAXN * 64];
__device__ __align__(16) float g_h1[(size_t)MAXN * 64];
__device__ float g_inv[MAXN];
__device__ float g_s[MAXN];
__device__ float g_t[MAXN];
__device__ int   g_degi[MAXN];
__device__ int   g_off[MAXN];
__device__ int   g_cur[MAXN];
__device__ int   g_csr[MAXE];
__device__ unsigned long long g_look[MAXNB];  // decoupled-lookback words

// ---------------- packed f32x2 helpers ---------------------------------------
__device__ __forceinline__ unsigned long long pack2(float x, float y) {
    unsigned long long r;
    asm("mov.b64 %0, {%1, %2};" : "=l"(r) : "f"(x), "f"(y));
    return r;
}
__device__ __forceinline__ void fma2(unsigned long long& d,
                                     unsigned long long a,
                                     unsigned long long b) {
    asm("fma.rn.f32x2 %0, %1, %2, %0;" : "+l"(d) : "l"(a), "l"(b));
}
__device__ __forceinline__ float2 unpack2(unsigned long long r) {
    float2 f;
    asm("mov.b64 {%0, %1}, %2;" : "=f"(f.x), "=f"(f.y) : "l"(r));
    return f;
}

// ---------------- per-block int64/int32 edge-index detect --------------------
__device__ __forceinline__ int block_detect_is64(const void* ei, int* s_is64) {
    if (threadIdx.x == 0) {
        const int* p = (const int*)ei;
        int is64 = 1;
#pragma unroll
        for (int q = 1; q < 32; q += 2)
            if (p[q] != 0) is64 = 0;
        *s_is64 = is64;
    }
    __syncthreads();
    return *s_is64;
}

// ---------------- degree histogram ------------------------------------------
__global__ void k_count(const void* __restrict__ ei, int E) {
    __shared__ int s_is64;
    int is64 = block_detect_is64(ei, &s_is64);
    for (int e = blockIdx.x * blockDim.x + threadIdx.x; e < E;
         e += gridDim.x * blockDim.x) {
        int d;
        if (is64) d = (int)((const long long*)ei)[(long)E + e];
        else      d = ((const int*)ei)[(long)E + e];
        atomicAdd(&g_degi[d], 1);
    }
}

// ---------------- single-kernel exclusive scan (decoupled lookback) ---------
// g_look[b] = (state<<32) | value; state 1 = block aggregate, 2 = inclusive.
__global__ void k_scan(int N) {
    __shared__ int sw[16];
    __shared__ int s_prev;
    int tid = threadIdx.x;
    int lane = tid & 31, wid = tid >> 5;
    int n = blockIdx.x * SCAN_CH + tid;
    int dg = (n < N) ? g_degi[n] : 0;
    int v = dg;
#pragma unroll
    for (int o = 1; o < 32; o <<= 1) {
        int t = __shfl_up_sync(0xffffffffu, v, o);
        if (lane >= o) v += t;
    }
    if (lane == 31) sw[wid] = v;
    __syncthreads();
    if (wid == 0) {
        int t = (lane < 16) ? sw[lane] : 0;
        int u = t;
#pragma unroll
        for (int o = 1; o < 16; o <<= 1) {
            int q = __shfl_up_sync(0xffffffffu, u, o);
            if (lane >= o) u += q;
        }
        if (lane < 16) sw[lane] = u - t;  // exclusive warp offsets
        int total = __shfl_sync(0xffffffffu, u, 15);
        if (lane == 0) {
            int b = blockIdx.x;
            int acc = 0;
            if (b == 0) {
                atomicExch(&g_look[0],
                           (2ull << 32) | (unsigned int)total);
            } else {
                atomicExch(&g_look[b],
                           (1ull << 32) | (unsigned int)total);
                int i = b - 1;
                while (i >= 0) {
                    unsigned long long w = atomicAdd(&g_look[i], 0ull);
                    int st = (int)(w >> 32);
                    if (st == 0) continue;  // spin: predecessor not ready
                    acc += (int)(w & 0xffffffffu);
                    if (st == 2) break;
                    i--;
                }
                atomicExch(&g_look[b],
                           (2ull << 32) | (unsigned int)(acc + total));
            }
            s_prev = acc;
        }
    }
    __syncthreads();
    if (n < N) {
        int off = s_prev + sw[wid] + v - dg;
        g_off[n] = off;
        g_cur[n] = off;
        g_inv[n] = 1.0f / fmaxf((float)dg, 1.0f);
    }
}

// ---------------- CSR fill ----------------------------------------------------
__global__ void k_fill(const void* __restrict__ ei, int E) {
    __shared__ int s_is64;
    int is64 = block_detect_is64(ei, &s_is64);
    for (int e = blockIdx.x * blockDim.x + threadIdx.x; e < E;
         e += gridDim.x * blockDim.x) {
        int sN, d;
        if (is64) {
            const long long* p = (const long long*)ei;
            sN = (int)p[e];
            d = (int)p[(long)E + e];
        } else {
            const int* p = (const int*)ei;
            sN = p[e];
            d = p[(long)E + e];
        }
        int pos = atomicAdd(&g_cur[d], 1);
        g_csr[pos] = sN;
    }
}

// ---------------- layer-1 mean aggregation (warp per node, 4x unroll) -------
__global__ void k_aggmean32(const float* __restrict__ feat, int N) {
    int warp = (blockIdx.x * blockDim.x + threadIdx.x) >> 5;
    int lane = threadIdx.x & 31;
    if (warp >= N) return;
    int beg = g_off[warp];
    int end = beg + g_degi[warp];
    float iv = g_inv[warp];
    float a0 = 0.f, a1 = 0.f;
    int j = beg;
    for (; j + 3 < end; j += 4) {
        int s0 = g_csr[j], s1 = g_csr[j + 1];
        int s2 = g_csr[j + 2], s3 = g_csr[j + 3];
        a0 += feat[(long)s0 * 32 + lane] + feat[(long)s1 * 32 + lane];
        a1 += feat[(long)s2 * 32 + lane] + feat[(long)s3 * 32 + lane];
    }
    for (; j < end; j++) a0 += feat[(long)g_csr[j] * 32 + lane];
    g_agg[(long)warp * 32 + lane] = (a0 + a1) * iv;
}

// ---------------- layer-2 mean aggregation (f32 h1, warp per node) ----------
__global__ void k_aggmean64(int N) {
    int warp = (blockIdx.x * blockDim.x + threadIdx.x) >> 5;
    int lane = threadIdx.x & 31;
    if (warp >= N) return;
    int beg = g_off[warp];
    int end = beg + g_degi[warp];
    float iv = g_inv[warp];
    const float2* f2 = (const float2*)g_h1;
    float2 a0 = make_float2(0.f, 0.f), a1 = make_float2(0.f, 0.f);
    int j = beg;
    for (; j + 3 < end; j += 4) {
        int s0 = g_csr[j], s1 = g_csr[j + 1];
        int s2 = g_csr[j + 2], s3 = g_csr[j + 3];
        float2 p = f2[(long)s0 * 32 + lane];
        float2 q = f2[(long)s1 * 32 + lane];
        float2 r = f2[(long)s2 * 32 + lane];
        float2 w = f2[(long)s3 * 32 + lane];
        a0.x += p.x + q.x; a0.y += p.y + q.y;
        a1.x += r.x + w.x; a1.y += r.y + w.y;
    }
    for (; j < end; j++) {
        float2 p = f2[(long)g_csr[j] * 32 + lane];
        a0.x += p.x; a0.y += p.y;
    }
    ((float2*)g_agg)[(long)warp * 32 + lane] =
        make_float2((a0.x + a1.x) * iv, (a0.y + a1.y) * iv);
}

// ---------------- fused SAGE layer GEMM (packed f32x2, float2 k-loads) -------
// LAYER 1: relu -> g_h1. LAYER 2: relu consumed in-register by fused wl3/wr3
// projection -> g_s, g_t (h2 never materialized).
template <int KH, int LAYER>
__global__ void k_gemm(const float* __restrict__ fbx,
                       const float* __restrict__ wl,
                       const float* __restrict__ wr,
                       const float* __restrict__ bias,
                       const float* __restrict__ wl3,
                       const float* __restrict__ wr3, int N) {
    constexpr int COUT = 64;
    const float* fb = (LAYER == 1) ? fbx : g_h1;

    __shared__ float swl[KH][COUT];
    __shared__ float swr[KH][COUT];
    __shared__ float sl3[64], sr3[64];
    for (int i = threadIdx.x; i < KH * COUT; i += blockDim.x) {
        int o = i / KH, k = i % KH;
        swl[k][o] = wl[i];
        swr[k][o] = wr[i];
    }
    if (LAYER == 2 && threadIdx.x < 64) {
        sl3[threadIdx.x] = wl3[threadIdx.x];
        sr3[threadIdx.x] = wr3[threadIdx.x];
    }
    __syncthreads();

    int og = (threadIdx.x & 3) * 16;
    int nb = blockIdx.x * 128 + (threadIdx.x >> 2) * 4;

    int idx[4];
#pragma unroll
    for (int i = 0; i < 4; i++) idx[i] = min(nb + i, N - 1);

    unsigned long long acc2[4][8];
#pragma unroll
    for (int i = 0; i < 4; i++)
#pragma unroll
        for (int j = 0; j < 8; j++) acc2[i][j] = 0ull;

    for (int k = 0; k < KH; k += 2) {
        unsigned long long va[4][2], vb[4][2];
#pragma unroll
        for (int i = 0; i < 4; i++) {
            float2 a = *(const float2*)(g_agg + (long)idx[i] * KH + k);
            float2 b = *(const float2*)(fb + (long)idx[i] * KH + k);
            va[i][0] = pack2(a.x, a.x);
            va[i][1] = pack2(a.y, a.y);
            vb[i][0] = pack2(b.x, b.x);
            vb[i][1] = pack2(b.y, b.y);
        }
#pragma unroll
        for (int j = 0; j < 8; j++) {
            unsigned long long w0 = *(const unsigned long long*)&swl[k][og + 2 * j];
            unsigned long long w1 = *(const unsigned long long*)&swl[k + 1][og + 2 * j];
            unsigned long long u0 = *(const unsigned long long*)&swr[k][og + 2 * j];
            unsigned long long u1 = *(const unsigned long long*)&swr[k + 1][og + 2 * j];
#pragma unroll
            for (int i = 0; i < 4; i++) {
                fma2(acc2[i][j], va[i][0], w0);
                fma2(acc2[i][j], va[i][1], w1);
                fma2(acc2[i][j], vb[i][0], u0);
                fma2(acc2[i][j], vb[i][1], u1);
            }
        }
    }

    const float2* bias2 = (const float2*)bias;
    float ps[4], pt[4];
#pragma unroll
    for (int i = 0; i < 4; i++) { ps[i] = 0.f; pt[i] = 0.f; }

#pragma unroll
    for (int i = 0; i < 4; i++) {
#pragma unroll
        for (int j = 0; j < 8; j++) {
            float2 v = unpack2(acc2[i][j]);
            float2 bv = bias2[og / 2 + j];
            float o0 = fmaxf(v.x + bv.x, 0.0f);
            float o1 = fmaxf(v.y + bv.y, 0.0f);
            if (LAYER == 1) {
                if (nb + i < N)
                    *(float2*)(g_h1 + (long)(nb + i) * 64 + og + 2 * j) =
                        make_float2(o0, o1);
            } else {
                ps[i] += o0 * sl3[og + 2 * j] + o1 * sl3[og + 2 * j + 1];
                pt[i] += o0 * sr3[og + 2 * j] + o1 * sr3[og + 2 * j + 1];
            }
        }
    }

    if (LAYER == 2) {
#pragma unroll
        for (int i = 0; i < 4; i++) {
#pragma unroll
            for (int o = 1; o <= 2; o <<= 1) {
                ps[i] += __shfl_xor_sync(0xffffffffu, ps[i], o);
                pt[i] += __shfl_xor_sync(0xffffffffu, pt[i], o);
            }
        }
        if ((threadIdx.x & 3) == 0) {
#pragma unroll
            for (int i = 0; i < 4; i++) {
                if (nb + i < N) {
                    g_s[nb + i] = ps[i];
                    g_t[nb + i] = pt[i];
                }
            }
        }
    }
}

// ---------------- layer-3: CSR scalar agg + sigmoid + state reset -----------
__global__ void k_out3(const float* __restrict__ b3, float* __restrict__ out,
                       int N) {
    // reset lookback words for the next launch (state invariant)
    if (blockIdx.x < MAXNB && threadIdx.x == 0) g_look[blockIdx.x] = 0ull;

    int warp = (blockIdx.x * blockDim.x + threadIdx.x) >> 5;
    int lane = threadIdx.x & 31;
    if (warp >= N) return;
    int beg = g_off[warp];
    int end = beg + g_degi[warp];
    float acc = 0.0f;
    for (int j = beg + lane; j < end; j += 32) acc += g_s[g_csr[j]];
#pragma unroll
    for (int o = 16; o > 0; o >>= 1)
        acc += __shfl_xor_sync(0xffffffffu, acc, o);
    if (lane == 0) {
        float z = acc * g_inv[warp] + b3[0] + g_t[warp];
        out[warp] = 1.0f / (1.0f + expf(-z));
        g_degi[warp] = 0;  // reset degree for the next launch
    }
}

// ---------------- launch -----------------------------------------------------
extern "C" void kernel_launch(void* const* d_in, const int* in_sizes, int n_in,
                              void* d_out, int out_size) {
    const float* x   = (const float*)d_in[0];
    const void*  ei  = d_in[1];
    const float* wl1 = (const float*)d_in[2];
    const float* wr1 = (const float*)d_in[3];
    const float* b1  = (const float*)d_in[4];
    const float* wl2 = (const float*)d_in[5];
    const float* wr2 = (const float*)d_in[6];
    const float* b2  = (const float*)d_in[7];
    const float* wl3 = (const float*)d_in[8];
    const float* wr3 = (const float*)d_in[9];
    const float* b3  = (const float*)d_in[10];
    float* out = (float*)d_out;

    int N = in_sizes[0] / 32;
    int E = in_sizes[1] / 2;
    int NB = (N + SCAN_CH - 1) / SCAN_CH;

    // ---- CSR build (g_degi/g_look zero on entry; k_out3 restores) ----
    k_count<<<(E + 255) / 256, 256>>>(ei, E);
    k_scan<<<NB, SCAN_CH>>>(N);
    k_fill<<<(E + 255) / 256, 256>>>(ei, E);

    // ---- layer 1 ----
    k_aggmean32<<<(N * 32 + 255) / 256, 256>>>(x, N);
    k_gemm<32, 1><<<(N + 127) / 128, 128>>>(x, wl1, wr1, b1, wl3, wr3, N);

    // ---- layer 2 (h2 never stored) ----
    k_aggmean64<<<(N * 32 + 255) / 256, 256>>>(N);
    k_gemm<64, 2><<<(N + 127) / 128, 128>>>(nullptr, wl2, wr2, b2, wl3, wr3, N);

    // ---- layer 3 output + state reset ----
    k_out3<<<(N * 32 + 255) / 256, 256>>>(b3, out, N);
}

// round 13
// speedup vs baseline: 1.0831x; 1.0831x over previous
#include <cuda_runtime.h>
#include <math.h>

#define MAXN 100000
#define MAXE 1600000
#define SCAN_CH 512
#define MAXNB 256   // >= ceil(MAXN/SCAN_CH) = 196

// ---------------- scratch (device-code-only globals; see round-2 postmortem)
// INVARIANT: g_degi and g_look are all-zero at entry of every kernel_launch.
// Statically zero-initialized for the first call; k_out3 re-zeroes them at the
// end of every call (graph replays therefore always start clean).
__device__ __align__(16) float g_agg[(size_t)MAXN * 64];
__device__ __align__(16) float g_h1[(size_t)MAXN * 64];
__device__ float g_inv[MAXN];
__device__ float g_s[MAXN];
__device__ float g_t[MAXN];
__device__ int   g_degi[MAXN];
__device__ int   g_off[MAXN];
__device__ __align__(16) int g_csr[MAXE];
__device__ int   g_rank[MAXE];
__device__ unsigned long long g_look[MAXNB];  // decoupled-lookback words

// ---------------- packed f32x2 helpers ---------------------------------------
__device__ __forceinline__ unsigned long long pack2(float x, float y) {
    unsigned long long r;
    asm("mov.b64 %0, {%1, %2};" : "=l"(r) : "f"(x), "f"(y));
    return r;
}
__device__ __forceinline__ void fma2(unsigned long long& d,
                                     unsigned long long a,
                                     unsigned long long b) {
    asm("fma.rn.f32x2 %0, %1, %2, %0;" : "+l"(d) : "l"(a), "l"(b));
}
__device__ __forceinline__ float2 unpack2(unsigned long long r) {
    float2 f;
    asm("mov.b64 {%0, %1}, %2;" : "=f"(f.x), "=f"(f.y) : "l"(r));
    return f;
}

// ---------------- per-block int64/int32 edge-index detect --------------------
__device__ __forceinline__ int block_detect_is64(const void* ei, int* s_is64) {
    if (threadIdx.x == 0) {
        const int* p = (const int*)ei;
        int is64 = 1;
#pragma unroll
        for (int q = 1; q < 32; q += 2)
            if (p[q] != 0) is64 = 0;
        *s_is64 = is64;
    }
    __syncthreads();
    return *s_is64;
}

// dst node id of edge e, reading only the low 32-bit word when int64.
__device__ __forceinline__ int load_dst(const void* ei, int E, int e, int is64) {
    const int* p = (const int*)ei;
    return is64 ? p[2 * ((long)E + e)] : p[(long)E + e];
}
__device__ __forceinline__ int load_src(const void* ei, int E, int e, int is64) {
    const int* p = (const int*)ei;
    return is64 ? p[2 * (long)e] : p[e];
}

// ---------------- degree histogram + per-edge rank ---------------------------
__global__ void k_count(const void* __restrict__ ei, int E) {
    __shared__ int s_is64;
    int is64 = block_detect_is64(ei, &s_is64);
    for (int e = blockIdx.x * blockDim.x + threadIdx.x; e < E;
         e += gridDim.x * blockDim.x) {
        int d = load_dst(ei, E, e, is64);
        g_rank[e] = atomicAdd(&g_degi[d], 1);
    }
}

// ---------------- single-kernel exclusive scan (decoupled lookback) ---------
// g_look[b] = (state<<32) | value; state 1 = block aggregate, 2 = inclusive.
__global__ void k_scan(int N) {
    __shared__ int sw[16];
    __shared__ int s_prev;
    int tid = threadIdx.x;
    int lane = tid & 31, wid = tid >> 5;
    int n = blockIdx.x * SCAN_CH + tid;
    int dg = (n < N) ? g_degi[n] : 0;
    int v = dg;
#pragma unroll
    for (int o = 1; o < 32; o <<= 1) {
        int t = __shfl_up_sync(0xffffffffu, v, o);
        if (lane >= o) v += t;
    }
    if (lane == 31) sw[wid] = v;
    __syncthreads();
    if (wid == 0) {
        int t = (lane < 16) ? sw[lane] : 0;
        int u = t;
#pragma unroll
        for (int o = 1; o < 16; o <<= 1) {
            int q = __shfl_up_sync(0xffffffffu, u, o);
            if (lane >= o) u += q;
        }
        if (lane < 16) sw[lane] = u - t;  // exclusive warp offsets
        int total = __shfl_sync(0xffffffffu, u, 15);
        if (lane == 0) {
            int b = blockIdx.x;
            int acc = 0;
            if (b == 0) {
                atomicExch(&g_look[0], (2ull << 32) | (unsigned int)total);
            } else {
                atomicExch(&g_look[b], (1ull << 32) | (unsigned int)total);
                int i = b - 1;
                while (i >= 0) {
                    unsigned long long w = atomicAdd(&g_look[i], 0ull);
                    int st = (int)(w >> 32);
                    if (st == 0) continue;  // spin: predecessor not ready
                    acc += (int)(w & 0xffffffffu);
                    if (st == 2) break;
                    i--;
                }
                atomicExch(&g_look[b],
                           (2ull << 32) | (unsigned int)(acc + total));
            }
            s_prev = acc;
        }
    }
    __syncthreads();
    if (n < N) {
        g_off[n] = s_prev + sw[wid] + v - dg;
        g_inv[n] = 1.0f / fmaxf((float)dg, 1.0f);
    }
}

// ---------------- CSR fill (atomic-free: offset + precomputed rank) ---------
__global__ void k_fill(const void* __restrict__ ei, int E) {
    __shared__ int s_is64;
    int is64 = block_detect_is64(ei, &s_is64);
    for (int e = blockIdx.x * blockDim.x + threadIdx.x; e < E;
         e += gridDim.x * blockDim.x) {
        int d = load_dst(ei, E, e, is64);
        int s = load_src(ei, E, e, is64);
        g_csr[g_off[d] + g_rank[e]] = s;
    }
}

// ---------------- layer-1 mean aggregation (warp/node, int4 csr loads) ------
__global__ void k_aggmean32(const float* __restrict__ feat, int N) {
    int warp = (blockIdx.x * blockDim.x + threadIdx.x) >> 5;
    unsigned lane = threadIdx.x & 31;
    if (warp >= N) return;
    int beg = g_off[warp];
    int end = beg + g_degi[warp];
    float iv = g_inv[warp];
    float a0 = 0.f, a1 = 0.f;
    int j = beg;
    // align to 4-edge boundary for int4 csr loads
    for (; j < end && (j & 3); j++)
        a0 += feat[(unsigned)g_csr[j] * 32u + lane];
    for (; j + 3 < end; j += 4) {
        int4 s4 = *(const int4*)(g_csr + j);
        a0 += feat[(unsigned)s4.x * 32u + lane] +
              feat[(unsigned)s4.y * 32u + lane];
        a1 += feat[(unsigned)s4.z * 32u + lane] +
              feat[(unsigned)s4.w * 32u + lane];
    }
    for (; j < end; j++)
        a0 += feat[(unsigned)g_csr[j] * 32u + lane];
    g_agg[(unsigned)warp * 32u + lane] = (a0 + a1) * iv;
}

// ---------------- layer-2 mean aggregation (f32 h1, warp/node, int4 csr) ----
__global__ void k_aggmean64(int N) {
    int warp = (blockIdx.x * blockDim.x + threadIdx.x) >> 5;
    unsigned lane = threadIdx.x & 31;
    if (warp >= N) return;
    int beg = g_off[warp];
    int end = beg + g_degi[warp];
    float iv = g_inv[warp];
    const float2* f2 = (const float2*)g_h1;
    float2 a0 = make_float2(0.f, 0.f), a1 = make_float2(0.f, 0.f);
    int j = beg;
    for (; j < end && (j & 3); j++) {
        float2 p = f2[(unsigned)g_csr[j] * 32u + lane];
        a0.x += p.x; a0.y += p.y;
    }
    for (; j + 3 < end; j += 4) {
        int4 s4 = *(const int4*)(g_csr + j);
        float2 p = f2[(unsigned)s4.x * 32u + lane];
        float2 q = f2[(unsigned)s4.y * 32u + lane];
        float2 r = f2[(unsigned)s4.z * 32u + lane];
        float2 w = f2[(unsigned)s4.w * 32u + lane];
        a0.x += p.x + q.x; a0.y += p.y + q.y;
        a1.x += r.x + w.x; a1.y += r.y + w.y;
    }
    for (; j < end; j++) {
        float2 p = f2[(unsigned)g_csr[j] * 32u + lane];
        a0.x += p.x; a0.y += p.y;
    }
    ((float2*)g_agg)[(unsigned)warp * 32u + lane] =
        make_float2((a0.x + a1.x) * iv, (a0.y + a1.y) * iv);
}

// ---------------- fused SAGE layer GEMM (packed f32x2, float2 k-loads) -------
// LAYER 1: relu -> g_h1. LAYER 2: relu consumed in-register by fused wl3/wr3
// projection -> g_s, g_t (h2 never materialized).
template <int KH, int LAYER>
__global__ void k_gemm(const float* __restrict__ fbx,
                       const float* __restrict__ wl,
                       const float* __restrict__ wr,
                       const float* __restrict__ bias,
                       const float* __restrict__ wl3,
                       const float* __restrict__ wr3, int N) {
    constexpr int COUT = 64;
    const float* fb = (LAYER == 1) ? fbx : g_h1;

    __shared__ float swl[KH][COUT];
    __shared__ float swr[KH][COUT];
    __shared__ float sl3[64], sr3[64];
    for (int i = threadIdx.x; i < KH * COUT; i += blockDim.x) {
        int o = i / KH, k = i % KH;
        swl[k][o] = wl[i];
        swr[k][o] = wr[i];
    }
    if (LAYER == 2 && threadIdx.x < 64) {
        sl3[threadIdx.x] = wl3[threadIdx.x];
        sr3[threadIdx.x] = wr3[threadIdx.x];
    }
    __syncthreads();

    int og = (threadIdx.x & 3) * 16;
    int nb = blockIdx.x * 128 + (threadIdx.x >> 2) * 4;

    int idx[4];
#pragma unroll
    for (int i = 0; i < 4; i++) idx[i] = min(nb + i, N - 1);

    unsigned long long acc2[4][8];
#pragma unroll
    for (int i = 0; i < 4; i++)
#pragma unroll
        for (int j = 0; j < 8; j++) acc2[i][j] = 0ull;

    for (int k = 0; k < KH; k += 2) {
        unsigned long long va[4][2], vb[4][2];
#pragma unroll
        for (int i = 0; i < 4; i++) {
            float2 a = *(const float2*)(g_agg + (unsigned)idx[i] * KH + k);
            float2 b = *(const float2*)(fb + (unsigned)idx[i] * KH + k);
            va[i][0] = pack2(a.x, a.x);
            va[i][1] = pack2(a.y, a.y);
            vb[i][0] = pack2(b.x, b.x);
            vb[i][1] = pack2(b.y, b.y);
        }
#pragma unroll
        for (int j = 0; j < 8; j++) {
            unsigned long long w0 = *(const unsigned long long*)&swl[k][og + 2 * j];
            unsigned long long w1 = *(const unsigned long long*)&swl[k + 1][og + 2 * j];
            unsigned long long u0 = *(const unsigned long long*)&swr[k][og + 2 * j];
            unsigned long long u1 = *(const unsigned long long*)&swr[k + 1][og + 2 * j];
#pragma unroll
            for (int i = 0; i < 4; i++) {
                fma2(acc2[i][j], va[i][0], w0);
                fma2(acc2[i][j], va[i][1], w1);
                fma2(acc2[i][j], vb[i][0], u0);
                fma2(acc2[i][j], vb[i][1], u1);
            }
        }
    }

    const float2* bias2 = (const float2*)bias;
    float ps[4], pt[4];
#pragma unroll
    for (int i = 0; i < 4; i++) { ps[i] = 0.f; pt[i] = 0.f; }

#pragma unroll
    for (int i = 0; i < 4; i++) {
#pragma unroll
        for (int j = 0; j < 8; j++) {
            float2 v = unpack2(acc2[i][j]);
            float2 bv = bias2[og / 2 + j];
            float o0 = fmaxf(v.x + bv.x, 0.0f);
            float o1 = fmaxf(v.y + bv.y, 0.0f);
            if (LAYER == 1) {
                if (nb + i < N)
                    *(float2*)(g_h1 + (unsigned)(nb + i) * 64 + og + 2 * j) =
                        make_float2(o0, o1);
            } else {
                ps[i] += o0 * sl3[og + 2 * j] + o1 * sl3[og + 2 * j + 1];
                pt[i] += o0 * sr3[og + 2 * j] + o1 * sr3[og + 2 * j + 1];
            }
        }
    }

    if (LAYER == 2) {
#pragma unroll
        for (int i = 0; i < 4; i++) {
#pragma unroll
            for (int o = 1; o <= 2; o <<= 1) {
                ps[i] += __shfl_xor_sync(0xffffffffu, ps[i], o);
                pt[i] += __shfl_xor_sync(0xffffffffu, pt[i], o);
            }
        }
        if ((threadIdx.x & 3) == 0) {
#pragma unroll
            for (int i = 0; i < 4; i++) {
                if (nb + i < N) {
                    g_s[nb + i] = ps[i];
                    g_t[nb + i] = pt[i];
                }
            }
        }
    }
}

// ---------------- layer-3: CSR scalar agg + sigmoid + state reset -----------
__global__ void k_out3(const float* __restrict__ b3, float* __restrict__ out,
                       int N) {
    // reset lookback words for the next launch (state invariant)
    if (blockIdx.x < MAXNB && threadIdx.x == 0) g_look[blockIdx.x] = 0ull;

    int warp = (blockIdx.x * blockDim.x + threadIdx.x) >> 5;
    int lane = threadIdx.x & 31;
    if (warp >= N) return;
    int beg = g_off[warp];
    int end = beg + g_degi[warp];
    float acc = 0.0f;
    for (int j = beg + lane; j < end; j += 32) acc += g_s[g_csr[j]];
#pragma unroll
    for (int o = 16; o > 0; o >>= 1)
        acc += __shfl_xor_sync(0xffffffffu, acc, o);
    if (lane == 0) {
        float z = acc * g_inv[warp] + b3[0] + g_t[warp];
        out[warp] = 1.0f / (1.0f + expf(-z));
        g_degi[warp] = 0;  // reset degree for the next launch
    }
}

// ---------------- launch -----------------------------------------------------
extern "C" void kernel_launch(void* const* d_in, const int* in_sizes, int n_in,
                              void* d_out, int out_size) {
    const float* x   = (const float*)d_in[0];
    const void*  ei  = d_in[1];
    const float* wl1 = (const float*)d_in[2];
    const float* wr1 = (const float*)d_in[3];
    const float* b1  = (const float*)d_in[4];
    const float* wl2 = (const float*)d_in[5];
    const float* wr2 = (const float*)d_in[6];
    const float* b2  = (const float*)d_in[7];
    const float* wl3 = (const float*)d_in[8];
    const float* wr3 = (const float*)d_in[9];
    const float* b3  = (const float*)d_in[10];
    float* out = (float*)d_out;

    int N = in_sizes[0] / 32;
    int E = in_sizes[1] / 2;
    int NB = (N + SCAN_CH - 1) / SCAN_CH;

    // ---- CSR build (g_degi/g_look zero on entry; k_out3 restores) ----
    k_count<<<(E + 255) / 256, 256>>>(ei, E);
    k_scan<<<NB, SCAN_CH>>>(N);
    k_fill<<<(E + 255) / 256, 256>>>(ei, E);

    // ---- layer 1 ----
    k_aggmean32<<<(N * 32 + 255) / 256, 256>>>(x, N);
    k_gemm<32, 1><<<(N + 127) / 128, 128>>>(x, wl1, wr1, b1, wl3, wr3, N);

    // ---- layer 2 (h2 never stored) ----
    k_aggmean64<<<(N * 32 + 255) / 256, 256>>>(N);
    k_gemm<64, 2><<<(N + 127) / 128, 128>>>(nullptr, wl2, wr2, b2, wl3, wr3, N);

    // ---- layer 3 output + state reset ----
    k_out3<<<(N * 32 + 255) / 256, 256>>>(b3, out, N);
}